// round 11
// baseline (speedup 1.0000x reference)
#include <cuda_runtime.h>
#include <cuda_fp16.h>
#include <cstdint>
#include <cstddef>

// ---------------- helpers ----------------
__device__ __forceinline__ uint32_t smem_u32(const void* p) {
    uint32_t a;
    asm("{ .reg .u64 t; cvta.to.shared.u64 t, %1; cvt.u32.u64 %0, t; }" : "=r"(a) : "l"(p));
    return a;
}
__device__ __forceinline__ void ldm_x4(uint32_t* r, uint32_t addr) {
    asm volatile("ldmatrix.sync.aligned.m8n8.x4.shared.b16 {%0,%1,%2,%3}, [%4];"
                 : "=r"(r[0]), "=r"(r[1]), "=r"(r[2]), "=r"(r[3]) : "r"(addr));
}
__device__ __forceinline__ void ldm_x4_t(uint32_t* r, uint32_t addr) {
    asm volatile("ldmatrix.sync.aligned.m8n8.x4.trans.shared.b16 {%0,%1,%2,%3}, [%4];"
                 : "=r"(r[0]), "=r"(r[1]), "=r"(r[2]), "=r"(r[3]) : "r"(addr));
}
__device__ __forceinline__ void mma_f16(float* c, const uint32_t* a, const uint32_t* b) {
    asm volatile("mma.sync.aligned.m16n8k16.row.col.f32.f16.f16.f32 "
                 "{%0,%1,%2,%3}, {%4,%5,%6,%7}, {%8,%9}, {%0,%1,%2,%3};"
                 : "+f"(c[0]), "+f"(c[1]), "+f"(c[2]), "+f"(c[3])
                 : "r"(a[0]), "r"(a[1]), "r"(a[2]), "r"(a[3]), "r"(b[0]), "r"(b[1]));
}
#define CP_ASYNC16(dst, src) \
    asm volatile("cp.async.cg.shared.global [%0], [%1], 16;" :: "r"(dst), "l"(src))
#define CP_COMMIT() asm volatile("cp.async.commit_group;" ::: "memory")
#define CP_WAIT1() asm volatile("cp.async.wait_group 1;" ::: "memory")
#define CP_WAIT0() asm volatile("cp.async.wait_group 0;" ::: "memory")

// ---------------- problem constants ----------------
#define NE 8388608            // 4*2048*1024
#define NS 16777216           // 4*2048*2048
#define WN 1048576            // 1024*1024

static constexpr int BK = 64;
static constexpr int SST  = 72;                     // A / B-Kmajor tile row stride (half): 144B
static constexpr int SSTB = 136;                    // B-trans tile row stride (half): 272B
static constexpr uint32_t MATB  = 128 * SST * 2;    // 18432: [128 rows][64 k]
static constexpr uint32_t MATBT = 64 * SSTB * 2;    // 17408: [64 k-rows][128 n]
static constexpr int NSTAGE = 3;

// ---------------- scratch (device globals) ----------------
__device__ __align__(256) __half g_x[3ull * NE];     // fp16 inputs
__device__ __align__(256) __half g_w[3ull * WN];     // W fp16, natural [d][n]
__device__ __align__(256) __half g_qkv[3ull * NE];   // Q/K/V fp16
__device__ __align__(256) float  g_S[NS];
__device__ __align__(256) __half g_ph[NS];           // softmax probs fp16
__device__ __align__(256) float  g_bias[3072];

// ---------------- small kernels ----------------
__global__ void pack_bias(const float* __restrict__ bq, const float* __restrict__ bk,
                          const float* __restrict__ bv, float* __restrict__ dst) {
    int i = blockIdx.x * blockDim.x + threadIdx.x;  // 0..3071
    const float* s = (i < 1024) ? bq : (i < 2048) ? bk : bv;
    dst[i] = s[i & 1023];
}

// fp32 -> fp16, three tensors of `per` elements each (z selects)
__global__ void cvt3(const float* __restrict__ a, const float* __restrict__ b,
                     const float* __restrict__ c, __half* __restrict__ o, size_t per) {
    const int z = blockIdx.z;
    const float* in = (z == 0) ? a : (z == 1) ? b : c;
    size_t li = ((size_t)blockIdx.x * blockDim.x + threadIdx.x) * 4;
    size_t i = (size_t)z * per + li;
    float4 vv = *reinterpret_cast<const float4*>(in + li);
    reinterpret_cast<__half2*>(o + i)[0] = __halves2half2(__float2half(vv.x), __float2half(vv.y));
    reinterpret_cast<__half2*>(o + i)[1] = __halves2half2(__float2half(vv.z), __float2half(vv.w));
}

// row softmax over 2048 -> fp16 probs
__global__ void softmax_h(const float* __restrict__ S, __half* __restrict__ ph) {
    const int row = blockIdx.x;
    const float* x = S + (size_t)row * 2048;
    const int tid = threadIdx.x;  // 256
    float v[8];
    float mx = -1e30f;
#pragma unroll
    for (int i = 0; i < 8; i++) { v[i] = x[tid + i * 256]; mx = fmaxf(mx, v[i]); }
#pragma unroll
    for (int o = 16; o; o >>= 1) mx = fmaxf(mx, __shfl_xor_sync(0xFFFFFFFFu, mx, o));
    __shared__ float redm[8], reds[8];
    if ((tid & 31) == 0) redm[tid >> 5] = mx;
    __syncthreads();
    float m2 = redm[0];
#pragma unroll
    for (int w = 1; w < 8; w++) m2 = fmaxf(m2, redm[w]);
    float s = 0.f;
#pragma unroll
    for (int i = 0; i < 8; i++) { v[i] = __expf(v[i] - m2); s += v[i]; }
#pragma unroll
    for (int o = 16; o; o >>= 1) s += __shfl_xor_sync(0xFFFFFFFFu, s, o);
    if ((tid & 31) == 0) reds[tid >> 5] = s;
    __syncthreads();
    float st = 0.f;
#pragma unroll
    for (int w = 0; w < 8; w++) st += reds[w];
    float inv = 1.f / st;
#pragma unroll
    for (int i = 0; i < 8; i++)
        ph[(size_t)row * 2048 + tid + i * 256] = __float2half(v[i] * inv);
}

// ---------------- HMMA fp16 GEMM: C[128x128]/CTA, 4 warps, BK=64, 3-stage ----------------
// TRANSB=0: B K-major [N][K]. TRANSB=1: B natural [K][N] via ldmatrix.trans.
// MODE 0: outH = fp16(val + bias[z*1024+col]) ; MODE 1: outF = val*scale (fp32).
template <int MODE, int TRANSB>
__global__ void __launch_bounds__(128, 2)
gemm_f16(const __half* __restrict__ A, const __half* __restrict__ B,
         int lda, int ldb, int ldc, int K,
         size_t aBatch, size_t bBatch, size_t cBatch,
         const float* __restrict__ bias, float scale,
         float* __restrict__ outF, __half* __restrict__ outH) {
    constexpr uint32_t BMAT = TRANSB ? MATBT : MATB;
    constexpr uint32_t STAGEB = MATB + BMAT;

    extern __shared__ char sm[];
    const uint32_t sbase = smem_u32(sm);
    const int tid = threadIdx.x;
    const int lane = tid & 31, wid = tid >> 5;
    const int wm = wid >> 1, wn = wid & 1;  // 2x2 warp grid, 64x64 tiles
    const int z = blockIdx.z;
    A += (size_t)z * aBatch;
    B += (size_t)z * bBatch;
    if (MODE == 0) { outH += (size_t)z * cBatch; bias += (size_t)z * 1024; }
    else           { outF += (size_t)z * cBatch; }

    const int mBase = blockIdx.y * 128;
    const int nBase = blockIdx.x * 128;
    const int KT = K / BK;

    auto issue_load = [&](int kb, int stage) {
        const int kOff = kb * BK;
        const uint32_t sb = sbase + (uint32_t)stage * STAGEB;
        // A tile: [128 m-rows][64 k] = 8 x 16B chunks per row
#pragma unroll
        for (int i = 0; i < 8; i++) {
            int idx = tid + i * 128;
            int r = idx >> 3, c = idx & 7;
            uint32_t daddr = sb + (uint32_t)(r * SST + c * 8) * 2;
            CP_ASYNC16(daddr, A + (size_t)(mBase + r) * lda + kOff + c * 8);
        }
        if (TRANSB) {
            // B tile: [64 k-rows][128 n] = 16 x 16B chunks per row
#pragma unroll
            for (int i = 0; i < 8; i++) {
                int idx = tid + i * 128;
                int r = idx >> 4, c = idx & 15;
                uint32_t daddr = sb + MATB + (uint32_t)(r * SSTB + c * 8) * 2;
                CP_ASYNC16(daddr, B + (size_t)(kOff + r) * ldb + nBase + c * 8);
            }
        } else {
            // B tile: [128 n-rows][64 k]
#pragma unroll
            for (int i = 0; i < 8; i++) {
                int idx = tid + i * 128;
                int r = idx >> 3, c = idx & 7;
                uint32_t daddr = sb + MATB + (uint32_t)(r * SST + c * 8) * 2;
                CP_ASYNC16(daddr, B + (size_t)(nBase + r) * ldb + kOff + c * 8);
            }
        }
        CP_COMMIT();
    };

    float acc[4][8][4];
#pragma unroll
    for (int i = 0; i < 4; i++)
#pragma unroll
        for (int j = 0; j < 8; j++)
#pragma unroll
            for (int e = 0; e < 4; e++) acc[i][j][e] = 0.f;

    // prologue: 2 stages in flight
    issue_load(0, 0);
    issue_load(1, 1);

    int stage = 0, stage2 = 2;
    for (int kb = 0; kb < KT; kb++) {
        if (kb + 1 < KT) { CP_WAIT1(); } else { CP_WAIT0(); }
        __syncthreads();
        if (kb + 2 < KT) issue_load(kb + 2, stage2);

        const uint32_t sb = sbase + (uint32_t)stage * STAGEB;
#pragma unroll
        for (int ks = 0; ks < 4; ks++) {
            uint32_t ah[4][4];
            const int rowA = wm * 64 + (lane & 15);
            const int colA = ks * 16 + (lane >> 4) * 8;
#pragma unroll
            for (int mt = 0; mt < 4; mt++) {
                uint32_t off = (uint32_t)((rowA + mt * 16) * SST + colA) * 2;
                ldm_x4(ah[mt], sb + off);
            }
#pragma unroll
            for (int bp = 0; bp < 4; bp++) {
                uint32_t th[4];
                if (TRANSB) {
                    const int kr = ks * 16 + (lane & 7) + (((lane >> 3) & 1) << 3);
                    const int nc = wn * 64 + bp * 16 + ((lane >> 4) << 3);
                    ldm_x4_t(th, sb + MATB + (uint32_t)(kr * SSTB + nc) * 2);
                } else {
                    const int rB = wn * 64 + bp * 16 + ((lane >> 4) << 3) + (lane & 7);
                    const int cB = ks * 16 + (((lane >> 3) & 1) << 3);
                    ldm_x4(th, sb + MATB + (uint32_t)(rB * SST + cB) * 2);
                }
#pragma unroll
                for (int mt = 0; mt < 4; mt++) {
                    mma_f16(acc[mt][bp * 2 + 0], ah[mt], th + 0);
                    mma_f16(acc[mt][bp * 2 + 1], ah[mt], th + 2);
                }
            }
        }
        stage  = (stage  == NSTAGE - 1) ? 0 : stage + 1;
        stage2 = (stage2 == NSTAGE - 1) ? 0 : stage2 + 1;
    }

    // epilogue
    const int g = lane >> 2, tq = lane & 3;
#pragma unroll
    for (int mt = 0; mt < 4; mt++) {
        const int row = mBase + wm * 64 + mt * 16 + g;
#pragma unroll
        for (int nt = 0; nt < 8; nt++) {
            const int col = nBase + wn * 64 + nt * 8 + tq * 2;
            const float* c = acc[mt][nt];
            if (MODE == 0) {
                float b0 = bias[col], b1 = bias[col + 1];
#pragma unroll
                for (int h = 0; h < 2; h++) {
                    size_t o = (size_t)(row + h * 8) * ldc + col;
                    *reinterpret_cast<__half2*>(outH + o) =
                        __halves2half2(__float2half(c[h * 2 + 0] + b0),
                                       __float2half(c[h * 2 + 1] + b1));
                }
            } else {
                float2 v0 = {c[0] * scale, c[1] * scale};
                float2 v1 = {c[2] * scale, c[3] * scale};
                *reinterpret_cast<float2*>(outF + (size_t)row * ldc + col) = v0;
                *reinterpret_cast<float2*>(outF + (size_t)(row + 8) * ldc + col) = v1;
            }
        }
    }
}

// ---------------- launch ----------------
extern "C" void kernel_launch(void* const* d_in, const int* in_sizes, int n_in,
                              void* d_out, int out_size) {
    const float* q_in = (const float*)d_in[0];
    const float* k_in = (const float*)d_in[1];
    const float* v_in = (const float*)d_in[2];
    const float* Wq   = (const float*)d_in[3];
    const float* bq   = (const float*)d_in[4];
    const float* Wk   = (const float*)d_in[5];
    const float* bk   = (const float*)d_in[6];
    const float* Wv   = (const float*)d_in[7];
    const float* bv   = (const float*)d_in[8];
    float* out = (float*)d_out;

    constexpr unsigned SMEM_T = NSTAGE * (MATB + MATBT);  // 107520
    constexpr unsigned SMEM_N = NSTAGE * (MATB + MATB);   // 110592
    cudaFuncSetAttribute((gemm_f16<0, 1>), cudaFuncAttributeMaxDynamicSharedMemorySize, SMEM_T);
    cudaFuncSetAttribute((gemm_f16<1, 0>), cudaFuncAttributeMaxDynamicSharedMemorySize, SMEM_N);
    cudaFuncSetAttribute((gemm_f16<1, 1>), cudaFuncAttributeMaxDynamicSharedMemorySize, SMEM_T);

    void* p;
    cudaGetSymbolAddress(&p, g_x);    __half* x  = (__half*)p;
    cudaGetSymbolAddress(&p, g_w);    __half* w  = (__half*)p;
    cudaGetSymbolAddress(&p, g_qkv);  __half* qkv = (__half*)p;
    cudaGetSymbolAddress(&p, g_S);    float* Sb = (float*)p;
    cudaGetSymbolAddress(&p, g_ph);   __half* ph = (__half*)p;
    cudaGetSymbolAddress(&p, g_bias); float* bias = (float*)p;

    pack_bias<<<12, 256>>>(bq, bk, bv, bias);
    cvt3<<<dim3(8192, 1, 3), 256>>>(q_in, k_in, v_in, x, (size_t)NE);
    cvt3<<<dim3(1024, 1, 3), 256>>>(Wq, Wk, Wv, w, (size_t)WN);
    // all 3 projections (z = q/k/v): [8192,1024] = X x W + b, W natural [d][n] via trans-B
    gemm_f16<0, 1><<<dim3(8, 64, 3), 128, SMEM_T>>>(
        x, w,
        1024, 1024, 1024, 1024,
        (size_t)NE, (size_t)WN, (size_t)NE,
        bias, 0.f, nullptr, qkv);
    // scores: S[2048,2048] = Q x K^T (K-proj is K-major), scale 1/32
    gemm_f16<1, 0><<<dim3(16, 16, 4), 128, SMEM_N>>>(
        qkv, qkv + NE,
        1024, 1024, 2048, 1024,
        (size_t)2048 * 1024, (size_t)2048 * 1024, (size_t)2048 * 2048,
        nullptr, 0.03125f, Sb, nullptr);
    softmax_h<<<8192, 256>>>(Sb, ph);
    // O = P x V, V natural [s][v] via trans-B
    gemm_f16<1, 1><<<dim3(8, 16, 4), 128, SMEM_T>>>(
        ph, qkv + 2ull * NE,
        2048, 1024, 1024, 2048,
        (size_t)2048 * 2048, (size_t)2048 * 1024, (size_t)2048 * 1024,
        nullptr, 1.0f, out, nullptr);
}

// round 12
// speedup vs baseline: 1.1231x; 1.1231x over previous
#include <cuda_runtime.h>
#include <cuda_fp16.h>
#include <cstdint>
#include <cstddef>

// ---------------- helpers ----------------
__device__ __forceinline__ uint32_t smem_u32(const void* p) {
    uint32_t a;
    asm("{ .reg .u64 t; cvta.to.shared.u64 t, %1; cvt.u32.u64 %0, t; }" : "=r"(a) : "l"(p));
    return a;
}
__device__ __forceinline__ void ldm_x4(uint32_t* r, uint32_t addr) {
    asm volatile("ldmatrix.sync.aligned.m8n8.x4.shared.b16 {%0,%1,%2,%3}, [%4];"
                 : "=r"(r[0]), "=r"(r[1]), "=r"(r[2]), "=r"(r[3]) : "r"(addr));
}
__device__ __forceinline__ void ldm_x4_t(uint32_t* r, uint32_t addr) {
    asm volatile("ldmatrix.sync.aligned.m8n8.x4.trans.shared.b16 {%0,%1,%2,%3}, [%4];"
                 : "=r"(r[0]), "=r"(r[1]), "=r"(r[2]), "=r"(r[3]) : "r"(addr));
}
__device__ __forceinline__ void mma_f16(float* c, const uint32_t* a, const uint32_t* b) {
    asm volatile("mma.sync.aligned.m16n8k16.row.col.f32.f16.f16.f32 "
                 "{%0,%1,%2,%3}, {%4,%5,%6,%7}, {%8,%9}, {%0,%1,%2,%3};"
                 : "+f"(c[0]), "+f"(c[1]), "+f"(c[2]), "+f"(c[3])
                 : "r"(a[0]), "r"(a[1]), "r"(a[2]), "r"(a[3]), "r"(b[0]), "r"(b[1]));
}
#define CP_ASYNC16(dst, src) \
    asm volatile("cp.async.cg.shared.global [%0], [%1], 16;" :: "r"(dst), "l"(src))
#define CP_COMMIT() asm volatile("cp.async.commit_group;" ::: "memory")
#define CP_WAIT3() asm volatile("cp.async.wait_group 3;" ::: "memory")
#define CP_WAIT2() asm volatile("cp.async.wait_group 2;" ::: "memory")
#define CP_WAIT1() asm volatile("cp.async.wait_group 1;" ::: "memory")
#define CP_WAIT0() asm volatile("cp.async.wait_group 0;" ::: "memory")

// ---------------- problem constants ----------------
#define NE 8388608            // 4*2048*1024
#define NS 16777216           // 4*2048*2048
#define WN 1048576            // 1024*1024

static constexpr int BK = 32;
static constexpr int SST  = 40;                     // A/B-Kmajor tile row stride (half): 80B
static constexpr int SSTB = 136;                    // B-trans tile row stride (half): 272B
static constexpr uint32_t MATB  = 128 * SST * 2;    // 10240: [128 rows][32 k]
static constexpr uint32_t MATBT = 32 * SSTB * 2;    // 8704:  [32 k-rows][128 n]
static constexpr int NSTAGE = 5;

// ---------------- scratch (device globals) ----------------
__device__ __align__(256) __half g_x[3ull * NE];     // fp16 inputs
__device__ __align__(256) __half g_w[3ull * WN];     // W fp16, natural [d][n]
__device__ __align__(256) __half g_qkv[3ull * NE];   // Q/K/V fp16
__device__ __align__(256) float  g_S[NS];
__device__ __align__(256) __half g_ph[NS];           // softmax probs fp16
__device__ __align__(256) float  g_bias[3072];

// ---------------- small kernels ----------------
__global__ void pack_bias(const float* __restrict__ bq, const float* __restrict__ bk,
                          const float* __restrict__ bv, float* __restrict__ dst) {
    int i = blockIdx.x * blockDim.x + threadIdx.x;  // 0..3071
    const float* s = (i < 1024) ? bq : (i < 2048) ? bk : bv;
    dst[i] = s[i & 1023];
}

// fp32 -> fp16, three tensors of `per` elements each (z selects)
__global__ void cvt3(const float* __restrict__ a, const float* __restrict__ b,
                     const float* __restrict__ c, __half* __restrict__ o, size_t per) {
    const int z = blockIdx.z;
    const float* in = (z == 0) ? a : (z == 1) ? b : c;
    size_t li = ((size_t)blockIdx.x * blockDim.x + threadIdx.x) * 4;
    size_t i = (size_t)z * per + li;
    float4 vv = *reinterpret_cast<const float4*>(in + li);
    reinterpret_cast<__half2*>(o + i)[0] = __halves2half2(__float2half(vv.x), __float2half(vv.y));
    reinterpret_cast<__half2*>(o + i)[1] = __halves2half2(__float2half(vv.z), __float2half(vv.w));
}

// row softmax over 2048 -> fp16 probs
__global__ void softmax_h(const float* __restrict__ S, __half* __restrict__ ph) {
    const int row = blockIdx.x;
    const float* x = S + (size_t)row * 2048;
    const int tid = threadIdx.x;  // 256
    float v[8];
    float mx = -1e30f;
#pragma unroll
    for (int i = 0; i < 8; i++) { v[i] = x[tid + i * 256]; mx = fmaxf(mx, v[i]); }
#pragma unroll
    for (int o = 16; o; o >>= 1) mx = fmaxf(mx, __shfl_xor_sync(0xFFFFFFFFu, mx, o));
    __shared__ float redm[8], reds[8];
    if ((tid & 31) == 0) redm[tid >> 5] = mx;
    __syncthreads();
    float m2 = redm[0];
#pragma unroll
    for (int w = 1; w < 8; w++) m2 = fmaxf(m2, redm[w]);
    float s = 0.f;
#pragma unroll
    for (int i = 0; i < 8; i++) { v[i] = __expf(v[i] - m2); s += v[i]; }
#pragma unroll
    for (int o = 16; o; o >>= 1) s += __shfl_xor_sync(0xFFFFFFFFu, s, o);
    if ((tid & 31) == 0) reds[tid >> 5] = s;
    __syncthreads();
    float st = 0.f;
#pragma unroll
    for (int w = 0; w < 8; w++) st += reds[w];
    float inv = 1.f / st;
#pragma unroll
    for (int i = 0; i < 8; i++)
        ph[(size_t)row * 2048 + tid + i * 256] = __float2half(v[i] * inv);
}

// ---------------- HMMA fp16 GEMM: C[128x128]/CTA, 4 warps, 5-stage pipeline ----------------
// TRANSB=0: B K-major [N][K]. TRANSB=1: B natural [K][N] via ldmatrix.trans.
// MODE 0: outH = fp16(val + bias[z*1024+col]) ; MODE 1: outF = val*scale (fp32).
// Inner loop: ALL 16 ldmatrix for the k-tile issued up front, then 64 dependency-free MMAs.
template <int MODE, int TRANSB>
__global__ void __launch_bounds__(128, 2)
gemm_f16(const __half* __restrict__ A, const __half* __restrict__ B,
         int lda, int ldb, int ldc, int K,
         size_t aBatch, size_t bBatch, size_t cBatch,
         const float* __restrict__ bias, float scale,
         float* __restrict__ outF, __half* __restrict__ outH) {
    constexpr uint32_t BMAT = TRANSB ? MATBT : MATB;
    constexpr uint32_t STAGEB = MATB + BMAT;

    extern __shared__ char sm[];
    const uint32_t sbase = smem_u32(sm);
    const int tid = threadIdx.x;
    const int lane = tid & 31, wid = tid >> 5;
    const int wm = wid >> 1, wn = wid & 1;  // 2x2 warp grid, 64x64 tiles
    const int z = blockIdx.z;
    A += (size_t)z * aBatch;
    B += (size_t)z * bBatch;
    if (MODE == 0) { outH += (size_t)z * cBatch; bias += (size_t)z * 1024; }
    else           { outF += (size_t)z * cBatch; }

    const int mBase = blockIdx.y * 128;
    const int nBase = blockIdx.x * 128;
    const int KT = K / BK;

    auto issue_load = [&](int kb, int stage) {
        const int kOff = kb * BK;
        const uint32_t sb = sbase + (uint32_t)stage * STAGEB;
        // A tile: [128 m-rows][32 k]
#pragma unroll
        for (int i = 0; i < 4; i++) {
            int idx = tid + i * 128;
            int r = idx >> 2, c = idx & 3;
            uint32_t daddr = sb + (uint32_t)(r * SST + c * 8) * 2;
            CP_ASYNC16(daddr, A + (size_t)(mBase + r) * lda + kOff + c * 8);
        }
        if (TRANSB) {
            // B tile: [32 k-rows][128 n]
#pragma unroll
            for (int i = 0; i < 4; i++) {
                int idx = tid + i * 128;
                int r = idx >> 4, c = idx & 15;
                uint32_t daddr = sb + MATB + (uint32_t)(r * SSTB + c * 8) * 2;
                CP_ASYNC16(daddr, B + (size_t)(kOff + r) * ldb + nBase + c * 8);
            }
        } else {
            // B tile: [128 n-rows][32 k]
#pragma unroll
            for (int i = 0; i < 4; i++) {
                int idx = tid + i * 128;
                int r = idx >> 2, c = idx & 3;
                uint32_t daddr = sb + MATB + (uint32_t)(r * SST + c * 8) * 2;
                CP_ASYNC16(daddr, B + (size_t)(nBase + r) * ldb + kOff + c * 8);
            }
        }
        CP_COMMIT();
    };

    float acc[4][8][4];
#pragma unroll
    for (int i = 0; i < 4; i++)
#pragma unroll
        for (int j = 0; j < 8; j++)
#pragma unroll
            for (int e = 0; e < 4; e++) acc[i][j][e] = 0.f;

    // prologue: 4 stages in flight
    issue_load(0, 0);
    issue_load(1, 1);
    issue_load(2, 2);
    issue_load(3, 3);

    int stage = 0, stage4 = 4;
    for (int kb = 0; kb < KT; kb++) {
        if (kb + 3 < KT)      { CP_WAIT3(); }
        else if (kb + 2 < KT) { CP_WAIT2(); }
        else if (kb + 1 < KT) { CP_WAIT1(); }
        else                  { CP_WAIT0(); }
        __syncthreads();
        if (kb + 4 < KT) issue_load(kb + 4, stage4);

        const uint32_t sb = sbase + (uint32_t)stage * STAGEB;

        // ---- load ALL fragments for this k-tile (16 ldmatrix, no consumers yet) ----
        uint32_t ah[2][4][4], th[2][4][4];
#pragma unroll
        for (int ks = 0; ks < 2; ks++) {
            const int rowA = wm * 64 + (lane & 15);
            const int colA = ks * 16 + (lane >> 4) * 8;
#pragma unroll
            for (int mt = 0; mt < 4; mt++)
                ldm_x4(ah[ks][mt], sb + (uint32_t)((rowA + mt * 16) * SST + colA) * 2);
#pragma unroll
            for (int bp = 0; bp < 4; bp++) {
                if (TRANSB) {
                    const int kr = ks * 16 + (lane & 7) + (((lane >> 3) & 1) << 3);
                    const int nc = wn * 64 + bp * 16 + ((lane >> 4) << 3);
                    ldm_x4_t(th[ks][bp], sb + MATB + (uint32_t)(kr * SSTB + nc) * 2);
                } else {
                    const int rB = wn * 64 + bp * 16 + ((lane >> 4) << 3) + (lane & 7);
                    const int cB = ks * 16 + (((lane >> 3) & 1) << 3);
                    ldm_x4(th[ks][bp], sb + MATB + (uint32_t)(rB * SST + cB) * 2);
                }
            }
        }
        // ---- 64 dependency-free MMAs ----
#pragma unroll
        for (int ks = 0; ks < 2; ks++)
#pragma unroll
            for (int bp = 0; bp < 4; bp++)
#pragma unroll
                for (int mt = 0; mt < 4; mt++) {
                    mma_f16(acc[mt][bp * 2 + 0], ah[ks][mt], th[ks][bp] + 0);
                    mma_f16(acc[mt][bp * 2 + 1], ah[ks][mt], th[ks][bp] + 2);
                }

        stage  = (stage  == NSTAGE - 1) ? 0 : stage + 1;
        stage4 = (stage4 == NSTAGE - 1) ? 0 : stage4 + 1;
    }

    // epilogue
    const int g = lane >> 2, tq = lane & 3;
#pragma unroll
    for (int mt = 0; mt < 4; mt++) {
        const int row = mBase + wm * 64 + mt * 16 + g;
#pragma unroll
        for (int nt = 0; nt < 8; nt++) {
            const int col = nBase + wn * 64 + nt * 8 + tq * 2;
            const float* c = acc[mt][nt];
            if (MODE == 0) {
                float b0 = bias[col], b1 = bias[col + 1];
#pragma unroll
                for (int h = 0; h < 2; h++) {
                    size_t o = (size_t)(row + h * 8) * ldc + col;
                    *reinterpret_cast<__half2*>(outH + o) =
                        __halves2half2(__float2half(c[h * 2 + 0] + b0),
                                       __float2half(c[h * 2 + 1] + b1));
                }
            } else {
                float2 v0 = {c[0] * scale, c[1] * scale};
                float2 v1 = {c[2] * scale, c[3] * scale};
                *reinterpret_cast<float2*>(outF + (size_t)row * ldc + col) = v0;
                *reinterpret_cast<float2*>(outF + (size_t)(row + 8) * ldc + col) = v1;
            }
        }
    }
}

// ---------------- launch ----------------
extern "C" void kernel_launch(void* const* d_in, const int* in_sizes, int n_in,
                              void* d_out, int out_size) {
    const float* q_in = (const float*)d_in[0];
    const float* k_in = (const float*)d_in[1];
    const float* v_in = (const float*)d_in[2];
    const float* Wq   = (const float*)d_in[3];
    const float* bq   = (const float*)d_in[4];
    const float* Wk   = (const float*)d_in[5];
    const float* bk   = (const float*)d_in[6];
    const float* Wv   = (const float*)d_in[7];
    const float* bv   = (const float*)d_in[8];
    float* out = (float*)d_out;

    constexpr unsigned SMEM_T = NSTAGE * (MATB + MATBT);  // 94720
    constexpr unsigned SMEM_N = NSTAGE * (MATB + MATB);   // 102400
    cudaFuncSetAttribute((gemm_f16<0, 1>), cudaFuncAttributeMaxDynamicSharedMemorySize, SMEM_T);
    cudaFuncSetAttribute((gemm_f16<1, 0>), cudaFuncAttributeMaxDynamicSharedMemorySize, SMEM_N);
    cudaFuncSetAttribute((gemm_f16<1, 1>), cudaFuncAttributeMaxDynamicSharedMemorySize, SMEM_T);

    void* p;
    cudaGetSymbolAddress(&p, g_x);    __half* x  = (__half*)p;
    cudaGetSymbolAddress(&p, g_w);    __half* w  = (__half*)p;
    cudaGetSymbolAddress(&p, g_qkv);  __half* qkv = (__half*)p;
    cudaGetSymbolAddress(&p, g_S);    float* Sb = (float*)p;
    cudaGetSymbolAddress(&p, g_ph);   __half* ph = (__half*)p;
    cudaGetSymbolAddress(&p, g_bias); float* bias = (float*)p;

    pack_bias<<<12, 256>>>(bq, bk, bv, bias);
    cvt3<<<dim3(8192, 1, 3), 256>>>(q_in, k_in, v_in, x, (size_t)NE);
    cvt3<<<dim3(1024, 1, 3), 256>>>(Wq, Wk, Wv, w, (size_t)WN);
    // all 3 projections (z = q/k/v): [8192,1024] = X x W + b, W natural [d][n] via trans-B
    gemm_f16<0, 1><<<dim3(8, 64, 3), 128, SMEM_T>>>(
        x, w,
        1024, 1024, 1024, 1024,
        (size_t)NE, (size_t)WN, (size_t)NE,
        bias, 0.f, nullptr, qkv);
    // scores: S[2048,2048] = Q x K^T (K-proj is K-major), scale 1/32
    gemm_f16<1, 0><<<dim3(16, 16, 4), 128, SMEM_N>>>(
        qkv, qkv + NE,
        1024, 1024, 2048, 1024,
        (size_t)2048 * 1024, (size_t)2048 * 1024, (size_t)2048 * 2048,
        nullptr, 0.03125f, Sb, nullptr);
    softmax_h<<<8192, 256>>>(Sb, ph);
    // O = P x V, V natural [s][v] via trans-B
    gemm_f16<1, 1><<<dim3(8, 16, 4), 128, SMEM_T>>>(
        ph, qkv + 2ull * NE,
        2048, 1024, 1024, 2048,
        (size_t)2048 * 2048, (size_t)2048 * 1024, (size_t)2048 * 1024,
        nullptr, 1.0f, out, nullptr);
}